// round 1
// baseline (speedup 1.0000x reference)
#include <cuda_runtime.h>
#include <cstdint>

// AdditiveAttention: B=2, L=512, S=512, H=8, E=32, D=64 (fp32)
// score[b,h,l,s] = sum_e tanh(q[b,l,h,e]+k[b,s,h,e])*v[e] + mask[l,s] + klen[b,s]
// A = softmax_s(score);  out[b,l,h,d] = sum_s A * values[b,s,h,d]

namespace {
constexpr int B = 2, L = 512, S = 512, H = 8, E = 32, D = 64;
constexpr int TL = 64;          // L-rows per CTA
constexpr int THREADS = 256;
constexpr int SC_STRIDE = S + 4; // pad: bank (4*l + s) % 32 -> conflict-free
constexpr int SMEM_FLOATS = TL * SC_STRIDE + S * E + TL * D + TL;
constexpr int SMEM_BYTES = SMEM_FLOATS * (int)sizeof(float);
constexpr float TWO_LOG2E = 2.885390081777927f; // 2*log2(e)
constexpr float LOG2E = 1.4426950408889634f;
}

__device__ __forceinline__ float ex2f(float x) {
    float y; asm("ex2.approx.f32 %0, %1;" : "=f"(y) : "f"(x)); return y;
}
__device__ __forceinline__ float rcpf(float x) {
    float y; asm("rcp.approx.f32 %0, %1;" : "=f"(y) : "f"(x)); return y;
}

__global__ void __launch_bounds__(THREADS, 1)
addattn_kernel(const float* __restrict__ q, const float* __restrict__ k,
               const float* __restrict__ vals, const float* __restrict__ vvec,
               const float* __restrict__ mask, const float* __restrict__ klen,
               float* __restrict__ out)
{
    extern __shared__ float sm[];
    float* sc   = sm;                    // [TL][SC_STRIDE] unnormalized probs
    float* ks   = sc + TL * SC_STRIDE;   // [S][E] keys pre-scaled by 2*log2(e)
    float* vs   = ks + S * E;            // [64][D] values chunk
    float* rsum = vs + TL * D;           // [TL] 1/rowsum

    const int tid = threadIdx.x;
    const int bid = blockIdx.x;
    const int lb = bid & 7;
    const int h  = (bid >> 3) & 7;
    const int b  = bid >> 6;
    const int l0 = lb * TL;

    // ---- load full keys slice for (b,h) into smem, pre-scaled by 2*log2e ----
    for (int i = tid; i < S * (E / 4); i += THREADS) {
        int s = i >> 3, e4 = i & 7;
        float4 t = reinterpret_cast<const float4*>(
            k + ((size_t)((b * S + s) * H + h)) * E)[e4];
        t.x *= TWO_LOG2E; t.y *= TWO_LOG2E; t.z *= TWO_LOG2E; t.w *= TWO_LOG2E;
        reinterpret_cast<float4*>(ks)[i] = t;
    }

    const int l   = tid >> 2;   // 0..63 local L row
    const int sof = tid & 3;    // s offset / d-group

    // ---- q row (pre-scaled) and v into registers ----
    float qr[E], vr[E];
    float vsumtot = 0.f;
    {
        const float4* qg = reinterpret_cast<const float4*>(
            q + ((size_t)((b * L + l0 + l) * H + h)) * E);
        const float4* vg = reinterpret_cast<const float4*>(vvec);
#pragma unroll
        for (int e4 = 0; e4 < E / 4; ++e4) {
            float4 t = qg[e4];
            qr[4*e4+0] = t.x * TWO_LOG2E; qr[4*e4+1] = t.y * TWO_LOG2E;
            qr[4*e4+2] = t.z * TWO_LOG2E; qr[4*e4+3] = t.w * TWO_LOG2E;
            float4 u = vg[e4];
            vr[4*e4+0] = u.x; vr[4*e4+1] = u.y; vr[4*e4+2] = u.z; vr[4*e4+3] = u.w;
            vsumtot += u.x + u.y + u.z + u.w;
        }
    }
    __syncthreads();

    // ---- phase 1: scores.  tanh(x) = 1 - 2/(1+e^{2x})
    // score = vsum - 2 * sum_e v_e / (1 + ex2(qs_e + ks_e)) + mask + klen
    {
        const float* maskrow = mask + (size_t)(l0 + l) * S;
        const float* klrow   = klen + (size_t)b * S;
        for (int j = 0; j < S / 4; ++j) {
            int s = 4 * j + sof;
            const float4* kr = reinterpret_cast<const float4*>(ks + s * E);
            float acc = 0.f;
#pragma unroll
            for (int e4 = 0; e4 < E / 4; ++e4) {
                float4 kk = kr[e4];
                acc += vr[4*e4+0] * rcpf(1.f + ex2f(qr[4*e4+0] + kk.x));
                acc += vr[4*e4+1] * rcpf(1.f + ex2f(qr[4*e4+1] + kk.y));
                acc += vr[4*e4+2] * rcpf(1.f + ex2f(qr[4*e4+2] + kk.z));
                acc += vr[4*e4+3] * rcpf(1.f + ex2f(qr[4*e4+3] + kk.w));
            }
            float score = vsumtot - 2.f * acc + maskrow[s] + klrow[s];
            sc[l * SC_STRIDE + s] = score;
        }
    }
    __syncthreads();

    // ---- phase 2: softmax over s (exp stored unnormalized; 1/sum kept) ----
    {
        const int warp = tid >> 5, lane = tid & 31;
        for (int r = warp * 8; r < warp * 8 + 8; ++r) {
            float* row = sc + r * SC_STRIDE;
            float vbuf[S / 32];
            float m = -1e30f;
#pragma unroll
            for (int i = 0; i < S / 32; ++i) {
                vbuf[i] = row[lane + 32 * i];
                m = fmaxf(m, vbuf[i]);
            }
#pragma unroll
            for (int o = 16; o > 0; o >>= 1) m = fmaxf(m, __shfl_xor_sync(0xffffffffu, m, o));
            float sum = 0.f;
#pragma unroll
            for (int i = 0; i < S / 32; ++i) {
                float p = ex2f((vbuf[i] - m) * LOG2E);
                sum += p;
                row[lane + 32 * i] = p;
            }
#pragma unroll
            for (int o = 16; o > 0; o >>= 1) sum += __shfl_xor_sync(0xffffffffu, sum, o);
            if (lane == 0) rsum[r] = rcpf(sum);
        }
    }
    __syncthreads();

    // ---- phase 3: out[l][d] = (sum_s P[l][s] * vals[s][d]) * rsum[l] ----
    {
        float acc[16];
#pragma unroll
        for (int i = 0; i < 16; ++i) acc[i] = 0.f;

        for (int c = 0; c < S / 64; ++c) {
            // cooperative load of 64 value rows into smem
            for (int i = tid; i < 64 * (D / 4); i += THREADS) {
                int ss = i >> 4, d4 = i & 15;
                float4 t = reinterpret_cast<const float4*>(
                    vals + ((size_t)((b * S + c * 64 + ss) * H + h)) * D)[d4];
                reinterpret_cast<float4*>(vs)[i] = t;
            }
            __syncthreads();

            const float* prow = sc + l * SC_STRIDE + c * 64;
#pragma unroll 4
            for (int ss = 0; ss < 64; ++ss) {
                float p = prow[ss];
                const float4* vrow = reinterpret_cast<const float4*>(vs + ss * D + sof * 16);
#pragma unroll
                for (int m4 = 0; m4 < 4; ++m4) {
                    float4 t = vrow[m4];
                    acc[4*m4+0] += p * t.x;
                    acc[4*m4+1] += p * t.y;
                    acc[4*m4+2] += p * t.z;
                    acc[4*m4+3] += p * t.w;
                }
            }
            __syncthreads();
        }

        const float r = rsum[l];
        float4* og = reinterpret_cast<float4*>(
            out + ((size_t)((b * L + l0 + l) * H + h)) * D + sof * 16);
#pragma unroll
        for (int m4 = 0; m4 < 4; ++m4) {
            og[m4] = make_float4(acc[4*m4+0] * r, acc[4*m4+1] * r,
                                 acc[4*m4+2] * r, acc[4*m4+3] * r);
        }
    }
}

extern "C" void kernel_launch(void* const* d_in, const int* in_sizes, int n_in,
                              void* d_out, int out_size)
{
    (void)in_sizes; (void)n_in; (void)out_size;
    cudaFuncSetAttribute(addattn_kernel,
                         cudaFuncAttributeMaxDynamicSharedMemorySize, SMEM_BYTES);
    const float* q    = (const float*)d_in[0];
    const float* k    = (const float*)d_in[1];
    const float* vals = (const float*)d_in[2];
    const float* vvec = (const float*)d_in[3];
    const float* mask = (const float*)d_in[4];
    const float* klen = (const float*)d_in[5];
    addattn_kernel<<<B * H * (L / TL), THREADS, SMEM_BYTES>>>(
        q, k, vals, vvec, mask, klen, (float*)d_out);
}

// round 2
// speedup vs baseline: 1.8564x; 1.8564x over previous
#include <cuda_runtime.h>
#include <cstdint>

// AdditiveAttention: B=2, L=512, S=512, H=8, E=32, D=64 (fp32)
// score = sum_e v_e*tanh(q+k) + mask + klen ; tanh(x) = 1 - 2/(1+e^{2x})
// e^{2x} = e^{2q} * e^{2k}  (precomputed factors -> 1 rcp per elem, 0.5 with pairing)

namespace {
constexpr int B = 2, L = 512, S = 512, H = 8, E = 32, D = 64;
constexpr int TL = 64;            // L-rows per CTA
constexpr int THREADS = 512;      // 16 warps
constexpr int SC_STRIDE = S + 8;  // 520: (8l+sof) distinct banks
constexpr int KS_STRIDE = E + 4;  // 36: 4s distinct bank groups
constexpr int SMEM_FLOATS = TL * SC_STRIDE + S * KS_STRIDE + TL * D + TL;
constexpr int SMEM_BYTES = SMEM_FLOATS * (int)sizeof(float);
constexpr float TWO_LOG2E = 2.885390081777927f; // 2*log2(e)
constexpr float LOG2E = 1.4426950408889634f;
}

__device__ __forceinline__ float ex2f(float x) {
    float y; asm("ex2.approx.f32 %0, %1;" : "=f"(y) : "f"(x)); return y;
}
__device__ __forceinline__ float rcpf(float x) {
    float y; asm("rcp.approx.f32 %0, %1;" : "=f"(y) : "f"(x)); return y;
}

__global__ void __launch_bounds__(THREADS, 1)
addattn_kernel(const float* __restrict__ q, const float* __restrict__ k,
               const float* __restrict__ vals, const float* __restrict__ vvec,
               const float* __restrict__ mask, const float* __restrict__ klen,
               float* __restrict__ out)
{
    extern __shared__ float sm[];
    float* sc   = sm;                     // [TL][SC_STRIDE] scores -> probs
    float* ks   = sc + TL * SC_STRIDE;    // [S][KS_STRIDE] exp2(c*k)
    float* vs   = ks + S * KS_STRIDE;     // [64][D] values chunk
    float* rsum = vs + TL * D;            // [TL] 1/rowsum

    const int tid = threadIdx.x;
    const int bid = blockIdx.x;
    const int lb = bid & 7;
    const int h  = (bid >> 3) & 7;
    const int b  = bid >> 6;
    const int l0 = lb * TL;

    // ---- stage keys as Ek = exp2(c*k) into smem (stride 36) ----
    for (int i = tid; i < S * (E / 4); i += THREADS) {
        int s = i >> 3, e4 = i & 7;
        float4 t = reinterpret_cast<const float4*>(
            k + ((size_t)((b * S + s) * H + h)) * E)[e4];
        t.x = ex2f(TWO_LOG2E * t.x); t.y = ex2f(TWO_LOG2E * t.y);
        t.z = ex2f(TWO_LOG2E * t.z); t.w = ex2f(TWO_LOG2E * t.w);
        *reinterpret_cast<float4*>(ks + s * KS_STRIDE + e4 * 4) = t;
    }

    const int l   = tid >> 3;   // 0..63 local L row
    const int sof = tid & 7;    // s offset within group of 8 / d sub-slice

    // ---- per-thread: Eq = exp2(c*q) and v into registers ----
    float qE[E], vr[E];
    float vsumtot = 0.f;
    {
        const float4* qg = reinterpret_cast<const float4*>(
            q + ((size_t)((b * L + l0 + l) * H + h)) * E);
        const float4* vg = reinterpret_cast<const float4*>(vvec);
#pragma unroll
        for (int e4 = 0; e4 < E / 4; ++e4) {
            float4 t = qg[e4];
            qE[4*e4+0] = ex2f(t.x * TWO_LOG2E); qE[4*e4+1] = ex2f(t.y * TWO_LOG2E);
            qE[4*e4+2] = ex2f(t.z * TWO_LOG2E); qE[4*e4+3] = ex2f(t.w * TWO_LOG2E);
            float4 u = vg[e4];
            vr[4*e4+0] = u.x; vr[4*e4+1] = u.y; vr[4*e4+2] = u.z; vr[4*e4+3] = u.w;
            vsumtot += u.x + u.y + u.z + u.w;
        }
    }
    __syncthreads();

    // ---- phase 1: scores.  score = vsum - 2*sum_e v_e/(1+Eq_e*Ek_e) + mask + klen
    // elems (x,y): paired fractions (1 rcp per 2); elems (z,w): simple (1 rcp each)
    {
        const float* maskrow = mask + (size_t)(l0 + l) * S;
        const float* klrow   = klen + (size_t)b * S;
        for (int j = 0; j < S / 8; ++j) {
            int s = 8 * j + sof;
            const float4* kr = reinterpret_cast<const float4*>(ks + s * KS_STRIDE);
            float accP = 0.f, accS0 = 0.f, accS1 = 0.f;
#pragma unroll
            for (int e4 = 0; e4 < E / 4; ++e4) {
                float4 kk = kr[e4];
                float v0 = vr[4*e4+0], v1 = vr[4*e4+1];
                // paired: v0/(1+u) + v1/(1+w) = [v0(1+w)+v1(1+u)] / [(1+u)(1+w)]
                float u  = qE[4*e4+0] * kk.x;
                float w  = qE[4*e4+1] * kk.y;
                float t2 = 1.f + (u + w);
                float den = fmaf(u, w, t2);
                float num = fmaf(v0, w, fmaf(v1, u, v0 + v1));
                accP = fmaf(num, rcpf(den), accP);
                // simple x2
                float t3 = fmaf(qE[4*e4+2], kk.z, 1.f);
                float t4 = fmaf(qE[4*e4+3], kk.w, 1.f);
                accS0 = fmaf(vr[4*e4+2], rcpf(t3), accS0);
                accS1 = fmaf(vr[4*e4+3], rcpf(t4), accS1);
            }
            float score = fmaf(-2.f, accP + accS0 + accS1,
                               vsumtot + maskrow[s] + klrow[s]);
            sc[l * SC_STRIDE + s] = score;
        }
    }
    __syncthreads();

    // ---- phase 2: softmax over s (store unnormalized probs; keep 1/sum) ----
    {
        const int warp = tid >> 5, lane = tid & 31;
#pragma unroll
        for (int r = warp * 4; r < warp * 4 + 4; ++r) {
            float* row = sc + r * SC_STRIDE;
            float vbuf[S / 32];
            float m = -1e30f;
#pragma unroll
            for (int i = 0; i < S / 32; ++i) {
                vbuf[i] = row[lane + 32 * i];
                m = fmaxf(m, vbuf[i]);
            }
#pragma unroll
            for (int o = 16; o > 0; o >>= 1) m = fmaxf(m, __shfl_xor_sync(0xffffffffu, m, o));
            float sum = 0.f;
#pragma unroll
            for (int i = 0; i < S / 32; ++i) {
                float p = ex2f((vbuf[i] - m) * LOG2E);
                sum += p;
                row[lane + 32 * i] = p;
            }
#pragma unroll
            for (int o = 16; o > 0; o >>= 1) sum += __shfl_xor_sync(0xffffffffu, sum, o);
            if (lane == 0) rsum[r] = rcpf(sum);
        }
    }
    __syncthreads();

    // ---- phase 3: out[l][d] = (sum_s P[l][s] * vals[s][d]) * rsum[l]
    // thread covers d in [4*sof, 4*sof+4) and [32+4*sof, 32+4*sof+4)
    {
        float acc[8];
#pragma unroll
        for (int i = 0; i < 8; ++i) acc[i] = 0.f;

        for (int c = 0; c < S / 64; ++c) {
            for (int i = tid; i < 64 * (D / 4); i += THREADS) {
                int ss = i >> 4, d4 = i & 15;
                float4 t = reinterpret_cast<const float4*>(
                    vals + ((size_t)((b * S + c * 64 + ss) * H + h)) * D)[d4];
                reinterpret_cast<float4*>(vs)[i] = t;
            }
            __syncthreads();

            const float* prow = sc + l * SC_STRIDE + c * 64;
#pragma unroll 4
            for (int ss = 0; ss < 64; ++ss) {
                float p = prow[ss];
                float4 t0 = *reinterpret_cast<const float4*>(vs + ss * D + sof * 4);
                float4 t1 = *reinterpret_cast<const float4*>(vs + ss * D + 32 + sof * 4);
                acc[0] = fmaf(p, t0.x, acc[0]); acc[1] = fmaf(p, t0.y, acc[1]);
                acc[2] = fmaf(p, t0.z, acc[2]); acc[3] = fmaf(p, t0.w, acc[3]);
                acc[4] = fmaf(p, t1.x, acc[4]); acc[5] = fmaf(p, t1.y, acc[5]);
                acc[6] = fmaf(p, t1.z, acc[6]); acc[7] = fmaf(p, t1.w, acc[7]);
            }
            __syncthreads();
        }

        const float r = rsum[l];
        float* og = out + ((size_t)((b * L + l0 + l) * H + h)) * D;
        *reinterpret_cast<float4*>(og + sof * 4) =
            make_float4(acc[0] * r, acc[1] * r, acc[2] * r, acc[3] * r);
        *reinterpret_cast<float4*>(og + 32 + sof * 4) =
            make_float4(acc[4] * r, acc[5] * r, acc[6] * r, acc[7] * r);
    }
}

extern "C" void kernel_launch(void* const* d_in, const int* in_sizes, int n_in,
                              void* d_out, int out_size)
{
    (void)in_sizes; (void)n_in; (void)out_size;
    cudaFuncSetAttribute(addattn_kernel,
                         cudaFuncAttributeMaxDynamicSharedMemorySize, SMEM_BYTES);
    const float* q    = (const float*)d_in[0];
    const float* k    = (const float*)d_in[1];
    const float* vals = (const float*)d_in[2];
    const float* vvec = (const float*)d_in[3];
    const float* mask = (const float*)d_in[4];
    const float* klen = (const float*)d_in[5];
    addattn_kernel<<<B * H * (L / TL), THREADS, SMEM_BYTES>>>(
        q, k, vals, vvec, mask, klen, (float*)d_out);
}

// round 3
// speedup vs baseline: 2.2623x; 1.2186x over previous
#include <cuda_runtime.h>
#include <cstdint>

// AdditiveAttention: B=2, L=512, S=512, H=8, E=32, D=64 (fp32)
// score = sum_e v_e*tanh(q+k) + mask + klen ; tanh(x) = 1 - 2/(1+e^{2x})
// e^{2x} = e^{2q}*e^{2k} (precomputed) -> pair/simple mix: 3 FMA + 0.75 MUFU /elem
// phase3: 4x8 register tiles, 4 s-subgroups + smem partial reduction

namespace {
constexpr int B = 2, L = 512, S = 512, H = 8, E = 32, D = 64;
constexpr int TL = 64;            // L-rows per CTA
constexpr int THREADS = 512;      // 16 warps
constexpr int SC_STRIDE = 524;    // phase1 STS conflict-free; phase3 P rows 2-way
constexpr int KS_STRIDE = E + 4;  // 36
constexpr int VS_STRIDE = 68;     // V chunk row stride
constexpr int PB_STRIDE = 68;     // partial buffer row stride
constexpr int SMEM_FLOATS = TL * SC_STRIDE + S * KS_STRIDE + 64 * VS_STRIDE + TL;
constexpr int SMEM_BYTES = SMEM_FLOATS * (int)sizeof(float);
constexpr float TWO_LOG2E = 2.885390081777927f; // 2*log2(e)
constexpr float LOG2E = 1.4426950408889634f;
}

__device__ __forceinline__ float ex2f(float x) {
    float y; asm("ex2.approx.f32 %0, %1;" : "=f"(y) : "f"(x)); return y;
}
__device__ __forceinline__ float rcpf(float x) {
    float y; asm("rcp.approx.f32 %0, %1;" : "=f"(y) : "f"(x)); return y;
}

__global__ void __launch_bounds__(THREADS, 1)
addattn_kernel(const float* __restrict__ q, const float* __restrict__ k,
               const float* __restrict__ vals, const float* __restrict__ vvec,
               const float* __restrict__ mask, const float* __restrict__ klen,
               float* __restrict__ out)
{
    extern __shared__ float sm[];
    float* sc   = sm;                     // [TL][SC_STRIDE] scores -> probs
    float* ks   = sc + TL * SC_STRIDE;    // [S][KS_STRIDE] exp2(c*k); reused as pbuf
    float* vs   = ks + S * KS_STRIDE;     // [64][VS_STRIDE] values chunk
    float* rsum = vs + 64 * VS_STRIDE;    // [TL] 1/rowsum

    const int tid = threadIdx.x;
    const int bid = blockIdx.x;
    const int lb = bid & 7;
    const int h  = (bid >> 3) & 7;
    const int b  = bid >> 6;
    const int l0 = lb * TL;

    // ---- stage keys as Ek = exp2(c*k) into smem ----
    for (int i = tid; i < S * (E / 4); i += THREADS) {
        int s = i >> 3, e4 = i & 7;
        float4 t = reinterpret_cast<const float4*>(
            k + ((size_t)((b * S + s) * H + h)) * E)[e4];
        t.x = ex2f(TWO_LOG2E * t.x); t.y = ex2f(TWO_LOG2E * t.y);
        t.z = ex2f(TWO_LOG2E * t.z); t.w = ex2f(TWO_LOG2E * t.w);
        *reinterpret_cast<float4*>(ks + s * KS_STRIDE + e4 * 4) = t;
    }

    const int l   = tid >> 3;   // 0..63 local L row (phases 1)
    const int sof = tid & 7;    // s offset within group of 8

    // ---- per-thread: Eq = exp2(c*q) and v into registers ----
    float qE[E], vr[E];
    float vsumtot = 0.f;
    {
        const float4* qg = reinterpret_cast<const float4*>(
            q + ((size_t)((b * L + l0 + l) * H + h)) * E);
        const float4* vg = reinterpret_cast<const float4*>(vvec);
#pragma unroll
        for (int e4 = 0; e4 < E / 4; ++e4) {
            float4 t = qg[e4];
            qE[4*e4+0] = ex2f(t.x * TWO_LOG2E); qE[4*e4+1] = ex2f(t.y * TWO_LOG2E);
            qE[4*e4+2] = ex2f(t.z * TWO_LOG2E); qE[4*e4+3] = ex2f(t.w * TWO_LOG2E);
            float4 u = vg[e4];
            vr[4*e4+0] = u.x; vr[4*e4+1] = u.y; vr[4*e4+2] = u.z; vr[4*e4+3] = u.w;
            vsumtot += u.x + u.y + u.z + u.w;
        }
    }
    __syncthreads();

    // ---- phase 1: score = vsum - 2*sum_e v_e/(1+Eq_e*Ek_e) + mask + klen ----
    {
        const float* maskrow = mask + (size_t)(l0 + l) * S;
        const float* klrow   = klen + (size_t)b * S;
        for (int j = 0; j < S / 8; ++j) {
            int s = 8 * j + sof;
            const float4* kr = reinterpret_cast<const float4*>(ks + s * KS_STRIDE);
            float accP = 0.f, accS0 = 0.f, accS1 = 0.f;
#pragma unroll
            for (int e4 = 0; e4 < E / 4; ++e4) {
                float4 kk = kr[e4];
                float v0 = vr[4*e4+0], v1 = vr[4*e4+1];
                float u  = qE[4*e4+0] * kk.x;
                float w  = qE[4*e4+1] * kk.y;
                float t2 = 1.f + (u + w);
                float den = fmaf(u, w, t2);
                float num = fmaf(v0, w, fmaf(v1, u, v0 + v1));
                accP = fmaf(num, rcpf(den), accP);
                float t3 = fmaf(qE[4*e4+2], kk.z, 1.f);
                float t4 = fmaf(qE[4*e4+3], kk.w, 1.f);
                accS0 = fmaf(vr[4*e4+2], rcpf(t3), accS0);
                accS1 = fmaf(vr[4*e4+3], rcpf(t4), accS1);
            }
            float score = fmaf(-2.f, accP + accS0 + accS1,
                               vsumtot + maskrow[s] + klrow[s]);
            sc[l * SC_STRIDE + s] = score;
        }
    }
    __syncthreads();

    // ---- phase 2: softmax over s (store unnormalized probs; keep 1/sum) ----
    {
        const int warp = tid >> 5, lane = tid & 31;
#pragma unroll
        for (int r = warp * 4; r < warp * 4 + 4; ++r) {
            float* row = sc + r * SC_STRIDE;
            float vbuf[S / 32];
            float m = -1e30f;
#pragma unroll
            for (int i = 0; i < S / 32; ++i) {
                vbuf[i] = row[lane + 32 * i];
                m = fmaxf(m, vbuf[i]);
            }
#pragma unroll
            for (int o = 16; o > 0; o >>= 1) m = fmaxf(m, __shfl_xor_sync(0xffffffffu, m, o));
            float sum = 0.f;
#pragma unroll
            for (int i = 0; i < S / 32; ++i) {
                float p = ex2f((vbuf[i] - m) * LOG2E);
                sum += p;
                row[lane + 32 * i] = p;
            }
#pragma unroll
            for (int o = 16; o > 0; o >>= 1) sum += __shfl_xor_sync(0xffffffffu, sum, o);
            if (lane == 0) rsum[r] = rcpf(sum);
        }
    }
    __syncthreads();

    // ---- phase 3: 4x8 register tile per thread, 4 s-subgroups ----
    {
        const int sgrp = tid >> 7;        // 0..3, owns ss%64 in [16*sgrp,16*sgrp+16)
        const int tt   = tid & 127;
        const int rg   = tt >> 3;         // 0..15 -> rows [4rg,4rg+4)
        const int cg   = tt & 7;          // 0..7  -> cols [8cg,8cg+8)

        float acc[4][8];
#pragma unroll
        for (int i = 0; i < 4; ++i)
#pragma unroll
            for (int d = 0; d < 8; ++d) acc[i][d] = 0.f;

        for (int c = 0; c < 8; ++c) {
            // stage 64 V rows
            for (int i = tid; i < 64 * (D / 4); i += THREADS) {
                int ss = i >> 4, d4 = i & 15;
                float4 t = reinterpret_cast<const float4*>(
                    vals + ((size_t)((b * S + c * 64 + ss) * H + h)) * D)[d4];
                *reinterpret_cast<float4*>(vs + ss * VS_STRIDE + d4 * 4) = t;
            }
            __syncthreads();

            const float* Pb = sc + (4 * rg) * SC_STRIDE + c * 64 + 16 * sgrp;
            const float* Vb = vs + (16 * sgrp) * VS_STRIDE + 8 * cg;
#pragma unroll
            for (int jb = 0; jb < 16; jb += 4) {
                float p4[4][4];
#pragma unroll
                for (int i = 0; i < 4; ++i) {
                    float4 p = *reinterpret_cast<const float4*>(Pb + i * SC_STRIDE + jb);
                    p4[i][0] = p.x; p4[i][1] = p.y; p4[i][2] = p.z; p4[i][3] = p.w;
                }
#pragma unroll
                for (int u = 0; u < 4; ++u) {
                    const float* vrow = Vb + (jb + u) * VS_STRIDE;
                    float4 v0 = *reinterpret_cast<const float4*>(vrow);
                    float4 v1 = *reinterpret_cast<const float4*>(vrow + 4);
#pragma unroll
                    for (int i = 0; i < 4; ++i) {
                        float p = p4[i][u];
                        acc[i][0] = fmaf(p, v0.x, acc[i][0]);
                        acc[i][1] = fmaf(p, v0.y, acc[i][1]);
                        acc[i][2] = fmaf(p, v0.z, acc[i][2]);
                        acc[i][3] = fmaf(p, v0.w, acc[i][3]);
                        acc[i][4] = fmaf(p, v1.x, acc[i][4]);
                        acc[i][5] = fmaf(p, v1.y, acc[i][5]);
                        acc[i][6] = fmaf(p, v1.z, acc[i][6]);
                        acc[i][7] = fmaf(p, v1.w, acc[i][7]);
                    }
                }
            }
            __syncthreads();
        }

        // write partials into pbuf (overlaid on dead ks region)
        float* pbuf = ks;  // [4][64][PB_STRIDE]
#pragma unroll
        for (int i = 0; i < 4; ++i) {
            int row = 4 * rg + i;
            float* dst = pbuf + (sgrp * 64 + row) * PB_STRIDE + 8 * cg;
            *reinterpret_cast<float4*>(dst) =
                make_float4(acc[i][0], acc[i][1], acc[i][2], acc[i][3]);
            *reinterpret_cast<float4*>(dst + 4) =
                make_float4(acc[i][4], acc[i][5], acc[i][6], acc[i][7]);
        }
        __syncthreads();

        // 4-way reduce + scale + store: thread -> (row, 8-col slice)
        {
            int row = tid >> 3;
            int c8  = (tid & 7) * 8;
            const float* p0 = pbuf + (0 * 64 + row) * PB_STRIDE + c8;
            const float* p1 = pbuf + (1 * 64 + row) * PB_STRIDE + c8;
            const float* p2 = pbuf + (2 * 64 + row) * PB_STRIDE + c8;
            const float* p3 = pbuf + (3 * 64 + row) * PB_STRIDE + c8;
            float r = rsum[row];
            float* og = out + ((size_t)((b * L + l0 + row) * H + h)) * D + c8;
#pragma unroll
            for (int half = 0; half < 2; ++half) {
                float4 a0 = *reinterpret_cast<const float4*>(p0 + 4 * half);
                float4 a1 = *reinterpret_cast<const float4*>(p1 + 4 * half);
                float4 a2 = *reinterpret_cast<const float4*>(p2 + 4 * half);
                float4 a3 = *reinterpret_cast<const float4*>(p3 + 4 * half);
                float4 o;
                o.x = ((a0.x + a1.x) + (a2.x + a3.x)) * r;
                o.y = ((a0.y + a1.y) + (a2.y + a3.y)) * r;
                o.z = ((a0.z + a1.z) + (a2.z + a3.z)) * r;
                o.w = ((a0.w + a1.w) + (a2.w + a3.w)) * r;
                *reinterpret_cast<float4*>(og + 4 * half) = o;
            }
        }
    }
}

extern "C" void kernel_launch(void* const* d_in, const int* in_sizes, int n_in,
                              void* d_out, int out_size)
{
    (void)in_sizes; (void)n_in; (void)out_size;
    cudaFuncSetAttribute(addattn_kernel,
                         cudaFuncAttributeMaxDynamicSharedMemorySize, SMEM_BYTES);
    const float* q    = (const float*)d_in[0];
    const float* k    = (const float*)d_in[1];
    const float* vals = (const float*)d_in[2];
    const float* vvec = (const float*)d_in[3];
    const float* mask = (const float*)d_in[4];
    const float* klen = (const float*)d_in[5];
    addattn_kernel<<<B * H * (L / TL), THREADS, SMEM_BYTES>>>(
        q, k, vals, vvec, mask, klen, (float*)d_out);
}

// round 4
// speedup vs baseline: 2.4605x; 1.0876x over previous
#include <cuda_runtime.h>
#include <cstdint>

// AdditiveAttention: B=2, L=512, S=512, H=8, E=32, D=64 (fp32)
// score = sum_e v_e*tanh(q+k) + mask + klen ; tanh(x) = 1 - 2/(1+e^{2x})
// e^{2x} = e^{2q}*e^{2k} (precomputed).  Pair identity:
//   v0/(1+u)+v1/(1+w) = [v01 + (v0 qE1)kk1 + (v1 qE0)kk0] / ((1+u)(1+w))
// exp folded into phase 1 (scores bounded by sum|v| -> no max pass needed).
// f32x2 packed FMA throughout to halve FMA-pipe issue.

namespace {
constexpr int B = 2, L = 512, S = 512, H = 8, E = 32, D = 64;
constexpr int TL = 64;
constexpr int THREADS = 512;
constexpr int SC_STRIDE = 524;
constexpr int KS_STRIDE = E + 4;   // 36
constexpr int VS_STRIDE = 68;
constexpr int PB_STRIDE = 68;
constexpr int SMEM_FLOATS = TL * SC_STRIDE + S * KS_STRIDE + 64 * VS_STRIDE + TL;
constexpr int SMEM_BYTES = SMEM_FLOATS * (int)sizeof(float);
constexpr float TWO_LOG2E = 2.885390081777927f; // 2*log2(e)
constexpr float LOG2E = 1.4426950408889634f;
}

using u64 = unsigned long long;

__device__ __forceinline__ float ex2f(float x) {
    float y; asm("ex2.approx.f32 %0, %1;" : "=f"(y) : "f"(x)); return y;
}
__device__ __forceinline__ float rcpf(float x) {
    float y; asm("rcp.approx.f32 %0, %1;" : "=f"(y) : "f"(x)); return y;
}
__device__ __forceinline__ u64 pk(float a, float b) {
    u64 d; asm("mov.b64 %0, {%1, %2};" : "=l"(d) : "f"(a), "f"(b)); return d;
}
__device__ __forceinline__ void upk(u64 d, float& a, float& b) {
    asm("mov.b64 {%0, %1}, %2;" : "=f"(a), "=f"(b) : "l"(d));
}
__device__ __forceinline__ u64 fma2(u64 a, u64 b, u64 c) {
    u64 d; asm("fma.rn.f32x2 %0, %1, %2, %3;" : "=l"(d) : "l"(a), "l"(b), "l"(c)); return d;
}
__device__ __forceinline__ u64 mul2(u64 a, u64 b) {
    u64 d; asm("mul.rn.f32x2 %0, %1, %2;" : "=l"(d) : "l"(a), "l"(b)); return d;
}
__device__ __forceinline__ u64 add2(u64 a, u64 b) {
    u64 d; asm("add.rn.f32x2 %0, %1, %2;" : "=l"(d) : "l"(a), "l"(b)); return d;
}

__global__ void __launch_bounds__(THREADS, 1)
addattn_kernel(const float* __restrict__ q, const float* __restrict__ k,
               const float* __restrict__ vals, const float* __restrict__ vvec,
               const float* __restrict__ mask, const float* __restrict__ klen,
               float* __restrict__ out)
{
    extern __shared__ float sm[];
    float* sc   = sm;                     // [TL][SC_STRIDE] unnormalized probs
    float* ks   = sc + TL * SC_STRIDE;    // [S][KS_STRIDE] exp2(c*k); reused as pbuf
    float* vs   = ks + S * KS_STRIDE;     // [64][VS_STRIDE] values chunk
    float* rsum = vs + 64 * VS_STRIDE;    // [TL] 1/rowsum

    const int tid = threadIdx.x;
    const int bid = blockIdx.x;
    const int lb = bid & 7;
    const int h  = (bid >> 3) & 7;
    const int b  = bid >> 6;
    const int l0 = lb * TL;

    // ---- stage keys as Ek = exp2(c*k) into smem ----
    for (int i = tid; i < S * (E / 4); i += THREADS) {
        int s = i >> 3, e4 = i & 7;
        float4 t = reinterpret_cast<const float4*>(
            k + ((size_t)((b * S + s) * H + h)) * E)[e4];
        t.x = ex2f(TWO_LOG2E * t.x); t.y = ex2f(TWO_LOG2E * t.y);
        t.z = ex2f(TWO_LOG2E * t.z); t.w = ex2f(TWO_LOG2E * t.w);
        *reinterpret_cast<float4*>(ks + s * KS_STRIDE + e4 * 4) = t;
    }

    const int l   = tid >> 3;   // 0..63 local L row
    const int sof = tid & 7;

    // ---- per-thread derived constants ----
    // per e4 group: qp01/qp23 (packed Eq pairs), cross-products for pair path,
    // packed v23 for the packed-simple path (odd e4).
    u64   qp01[8], qp23[8];
    float x01[8], x10[8], v01s[8];   // pair (0,1): v0*qE1, v1*qE0, v0+v1
    float x23[4], x32[4], v23s[4];   // even e4 pair (2,3)
    u64   v23p[4];                   // odd e4 packed (v2,v3)
    float vsumtot = 0.f;
    {
        const float4* qg = reinterpret_cast<const float4*>(
            q + ((size_t)((b * L + l0 + l) * H + h)) * E);
        const float4* vg = reinterpret_cast<const float4*>(vvec);
#pragma unroll
        for (int e4 = 0; e4 < 8; ++e4) {
            float4 t = qg[e4];
            float q0 = ex2f(t.x * TWO_LOG2E), q1 = ex2f(t.y * TWO_LOG2E);
            float q2 = ex2f(t.z * TWO_LOG2E), q3 = ex2f(t.w * TWO_LOG2E);
            qp01[e4] = pk(q0, q1);
            qp23[e4] = pk(q2, q3);
            float4 u = vg[e4];
            vsumtot += (u.x + u.y) + (u.z + u.w);
            x01[e4] = u.x * q1; x10[e4] = u.y * q0; v01s[e4] = u.x + u.y;
            if ((e4 & 1) == 0) {
                int i = e4 >> 1;
                x23[i] = u.z * q3; x32[i] = u.w * q2; v23s[i] = u.z + u.w;
            } else {
                v23p[e4 >> 1] = pk(u.z, u.w);
            }
        }
    }
    __syncthreads();

    const u64 ONES2 = pk(1.f, 1.f);

    // ---- phase 1: p = exp(score), fused; per-thread row partial sum ----
    {
        const float* maskrow = mask + (size_t)(l0 + l) * S;
        const float* klrow   = klen + (size_t)b * S;
        const float baseL = vsumtot * LOG2E;
        float psum = 0.f;
        for (int j = 0; j < S / 8; ++j) {
            int s = 8 * j + sof;
            const ulonglong2* kr = reinterpret_cast<const ulonglong2*>(ks + s * KS_STRIDE);
            float accP = 0.f;
            u64 accV = pk(0.f, 0.f);
#pragma unroll
            for (int e4 = 0; e4 < 8; ++e4) {
                ulonglong2 kk2 = kr[e4];
                // pair on elems (0,1)
                {
                    u64 uw = mul2(qp01[e4], kk2.x);
                    u64 opu = add2(uw, ONES2);           // (1+u, 1+w)
                    float a0, a1; upk(opu, a0, a1);
                    float den = a0 * a1;
                    float k0, k1; upk(kk2.x, k0, k1);
                    float num = fmaf(x01[e4], k1, fmaf(x10[e4], k0, v01s[e4]));
                    accP = fmaf(num, rcpf(den), accP);
                }
                if ((e4 & 1) == 0) {
                    // even: pair on elems (2,3) too
                    int i = e4 >> 1;
                    u64 uw = mul2(qp23[e4], kk2.y);
                    u64 opu = add2(uw, ONES2);
                    float a0, a1; upk(opu, a0, a1);
                    float den = a0 * a1;
                    float k2, k3; upk(kk2.y, k2, k3);
                    float num = fmaf(x23[i], k3, fmaf(x32[i], k2, v23s[i]));
                    accP = fmaf(num, rcpf(den), accP);
                } else {
                    // odd: packed-simple on elems (2,3)
                    u64 den2 = fma2(qp23[e4], kk2.y, ONES2);
                    float d2, d3; upk(den2, d2, d3);
                    u64 rp = pk(rcpf(d2), rcpf(d3));
                    accV = fma2(v23p[e4 >> 1], rp, accV);
                }
            }
            float vlo, vhi; upk(accV, vlo, vhi);
            float a = accP + (vlo + vhi);
            float mk = maskrow[s] + klrow[s];
            // score*log2e = baseL + mk*LOG2E - 2*LOG2E*a
            float p = ex2f(fmaf(-2.f * LOG2E, a, fmaf(LOG2E, mk, baseL)));
            psum += p;
            sc[l * SC_STRIDE + s] = p;
        }
        // reduce psum over the 8 sof lanes (warp-local groups)
        psum += __shfl_xor_sync(0xffffffffu, psum, 1);
        psum += __shfl_xor_sync(0xffffffffu, psum, 2);
        psum += __shfl_xor_sync(0xffffffffu, psum, 4);
        if (sof == 0) rsum[l] = rcpf(psum);
    }
    __syncthreads();

    // ---- phase 3: 4x8 register tile per thread, 4 s-subgroups, packed FMA ----
    {
        const int sgrp = tid >> 7;
        const int tt   = tid & 127;
        const int rg   = tt >> 3;
        const int cg   = tt & 7;

        u64 acc2[4][4];
#pragma unroll
        for (int i = 0; i < 4; ++i)
#pragma unroll
            for (int m = 0; m < 4; ++m) acc2[i][m] = pk(0.f, 0.f);

        for (int c = 0; c < 8; ++c) {
            for (int i = tid; i < 64 * (D / 4); i += THREADS) {
                int ss = i >> 4, d4 = i & 15;
                float4 t = reinterpret_cast<const float4*>(
                    vals + ((size_t)((b * S + c * 64 + ss) * H + h)) * D)[d4];
                *reinterpret_cast<float4*>(vs + ss * VS_STRIDE + d4 * 4) = t;
            }
            __syncthreads();

            const float* Pb = sc + (4 * rg) * SC_STRIDE + c * 64 + 16 * sgrp;
            const float* Vb = vs + (16 * sgrp) * VS_STRIDE + 8 * cg;
#pragma unroll
            for (int jb = 0; jb < 16; jb += 4) {
                float p4[4][4];
#pragma unroll
                for (int i = 0; i < 4; ++i) {
                    float4 p = *reinterpret_cast<const float4*>(Pb + i * SC_STRIDE + jb);
                    p4[i][0] = p.x; p4[i][1] = p.y; p4[i][2] = p.z; p4[i][3] = p.w;
                }
#pragma unroll
                for (int u = 0; u < 4; ++u) {
                    const ulonglong2* vrow =
                        reinterpret_cast<const ulonglong2*>(Vb + (jb + u) * VS_STRIDE);
                    ulonglong2 va = vrow[0];
                    ulonglong2 vb2 = vrow[1];
#pragma unroll
                    for (int i = 0; i < 4; ++i) {
                        u64 pp = pk(p4[i][u], p4[i][u]);
                        acc2[i][0] = fma2(va.x,  pp, acc2[i][0]);
                        acc2[i][1] = fma2(va.y,  pp, acc2[i][1]);
                        acc2[i][2] = fma2(vb2.x, pp, acc2[i][2]);
                        acc2[i][3] = fma2(vb2.y, pp, acc2[i][3]);
                    }
                }
            }
            __syncthreads();
        }

        // write partials (u64 stores, 16B aligned)
        float* pbuf = ks;  // [4][64][PB_STRIDE]
#pragma unroll
        for (int i = 0; i < 4; ++i) {
            int row = 4 * rg + i;
            u64* dst = reinterpret_cast<u64*>(
                pbuf + (sgrp * 64 + row) * PB_STRIDE + 8 * cg);
            reinterpret_cast<ulonglong2*>(dst)[0] = make_ulonglong2(acc2[i][0], acc2[i][1]);
            reinterpret_cast<ulonglong2*>(dst)[1] = make_ulonglong2(acc2[i][2], acc2[i][3]);
        }
        __syncthreads();

        // 4-way reduce + scale + store
        {
            int row = tid >> 3;
            int c8  = (tid & 7) * 8;
            const float* p0 = pbuf + (0 * 64 + row) * PB_STRIDE + c8;
            const float* p1 = pbuf + (1 * 64 + row) * PB_STRIDE + c8;
            const float* p2 = pbuf + (2 * 64 + row) * PB_STRIDE + c8;
            const float* p3 = pbuf + (3 * 64 + row) * PB_STRIDE + c8;
            float r = rsum[row];
            float* og = out + ((size_t)((b * L + l0 + row) * H + h)) * D + c8;
#pragma unroll
            for (int half = 0; half < 2; ++half) {
                float4 a0 = *reinterpret_cast<const float4*>(p0 + 4 * half);
                float4 a1 = *reinterpret_cast<const float4*>(p1 + 4 * half);
                float4 a2 = *reinterpret_cast<const float4*>(p2 + 4 * half);
                float4 a3 = *reinterpret_cast<const float4*>(p3 + 4 * half);
                float4 o;
                o.x = ((a0.x + a1.x) + (a2.x + a3.x)) * r;
                o.y = ((a0.y + a1.y) + (a2.y + a3.y)) * r;
                o.z = ((a0.z + a1.z) + (a2.z + a3.z)) * r;
                o.w = ((a0.w + a1.w) + (a2.w + a3.w)) * r;
                *reinterpret_cast<float4*>(og + 4 * half) = o;
            }
        }
    }
}

extern "C" void kernel_launch(void* const* d_in, const int* in_sizes, int n_in,
                              void* d_out, int out_size)
{
    (void)in_sizes; (void)n_in; (void)out_size;
    cudaFuncSetAttribute(addattn_kernel,
                         cudaFuncAttributeMaxDynamicSharedMemorySize, SMEM_BYTES);
    const float* q    = (const float*)d_in[0];
    const float* k    = (const float*)d_in[1];
    const float* vals = (const float*)d_in[2];
    const float* vvec = (const float*)d_in[3];
    const float* mask = (const float*)d_in[4];
    const float* klen = (const float*)d_in[5];
    addattn_kernel<<<B * H * (L / TL), THREADS, SMEM_BYTES>>>(
        q, k, vals, vvec, mask, klen, (float*)d_out);
}

// round 5
// speedup vs baseline: 2.6145x; 1.0626x over previous
#include <cuda_runtime.h>
#include <cstdint>

// AdditiveAttention: B=2, L=512, S=512, H=8, E=32, D=64 (fp32)
// score = sum_e v_e*tanh(q+k) + mask + klen ; tanh(x) = 1 - 2/(1+e^{2x})
// e^{2x} = e^{2q}*e^{2k} (precomputed).
// Quad combine: v0/(1+u0)+..+v3/(1+u3) = (numA*denB+numB*denA)/(denA*denB),
//   one rcp per 4 elems.  Groups 6,7 stay packed-simple to balance MUFU/FMA.
// exp fused into phase 1 (scores bounded by sum|v| -> no max pass).

namespace {
constexpr int B = 2, L = 512, S = 512, H = 8, E = 32, D = 64;
constexpr int TL = 64;
constexpr int THREADS = 512;
constexpr int SC_STRIDE = 524;
constexpr int KS_STRIDE = E + 4;   // 36
constexpr int VS_STRIDE = 68;
constexpr int PB_STRIDE = 68;
constexpr int SMEM_FLOATS = TL * SC_STRIDE + S * KS_STRIDE + 64 * VS_STRIDE + TL;
constexpr int SMEM_BYTES = SMEM_FLOATS * (int)sizeof(float);
constexpr float TWO_LOG2E = 2.885390081777927f; // 2*log2(e)
constexpr float LOG2E = 1.4426950408889634f;
}

using u64 = unsigned long long;

__device__ __forceinline__ float ex2f(float x) {
    float y; asm("ex2.approx.f32 %0, %1;" : "=f"(y) : "f"(x)); return y;
}
__device__ __forceinline__ float rcpf(float x) {
    float y; asm("rcp.approx.f32 %0, %1;" : "=f"(y) : "f"(x)); return y;
}
__device__ __forceinline__ u64 pk(float a, float b) {
    u64 d; asm("mov.b64 %0, {%1, %2};" : "=l"(d) : "f"(a), "f"(b)); return d;
}
__device__ __forceinline__ void upk(u64 d, float& a, float& b) {
    asm("mov.b64 {%0, %1}, %2;" : "=f"(a), "=f"(b) : "l"(d));
}
__device__ __forceinline__ u64 fma2(u64 a, u64 b, u64 c) {
    u64 d; asm("fma.rn.f32x2 %0, %1, %2, %3;" : "=l"(d) : "l"(a), "l"(b), "l"(c)); return d;
}
__device__ __forceinline__ u64 mul2(u64 a, u64 b) {
    u64 d; asm("mul.rn.f32x2 %0, %1, %2;" : "=l"(d) : "l"(a), "l"(b)); return d;
}
__device__ __forceinline__ u64 add2(u64 a, u64 b) {
    u64 d; asm("add.rn.f32x2 %0, %1, %2;" : "=l"(d) : "l"(a), "l"(b)); return d;
}

__global__ void __launch_bounds__(THREADS, 1)
addattn_kernel(const float* __restrict__ q, const float* __restrict__ k,
               const float* __restrict__ vals, const float* __restrict__ vvec,
               const float* __restrict__ mask, const float* __restrict__ klen,
               float* __restrict__ out)
{
    extern __shared__ float sm[];
    float* sc   = sm;                     // [TL][SC_STRIDE] unnormalized probs
    float* ks   = sc + TL * SC_STRIDE;    // [S][KS_STRIDE] exp2(c*k); reused as pbuf
    float* vs   = ks + S * KS_STRIDE;     // [64][VS_STRIDE] values chunk
    float* rsum = vs + 64 * VS_STRIDE;    // [TL] 1/rowsum

    const int tid = threadIdx.x;
    const int bid = blockIdx.x;
    const int lb = bid & 7;
    const int h  = (bid >> 3) & 7;
    const int b  = bid >> 6;
    const int l0 = lb * TL;

    // ---- stage keys as Ek = exp2(c*k) into smem ----
    for (int i = tid; i < S * (E / 4); i += THREADS) {
        int s = i >> 3, e4 = i & 7;
        float4 t = reinterpret_cast<const float4*>(
            k + ((size_t)((b * S + s) * H + h)) * E)[e4];
        t.x = ex2f(TWO_LOG2E * t.x); t.y = ex2f(TWO_LOG2E * t.y);
        t.z = ex2f(TWO_LOG2E * t.z); t.w = ex2f(TWO_LOG2E * t.w);
        *reinterpret_cast<float4*>(ks + s * KS_STRIDE + e4 * 4) = t;
    }

    const int l   = tid >> 3;   // 0..63 local L row
    const int sof = tid & 7;

    // ---- per-thread constants ----
    u64   qp01[8], qp23[8];                 // packed Eq pairs, thread-varying
    float v0c[6], v1c[6], v2c[6], v3c[6];   // quad groups 0..5 (uniform)
    float v01s[6], v23s[6];
    u64   vp01s[2], vp23s[2];               // simple groups 6,7 (uniform)
    float vsumtot = 0.f;
    {
        const float4* qg = reinterpret_cast<const float4*>(
            q + ((size_t)((b * L + l0 + l) * H + h)) * E);
        const float4* vg = reinterpret_cast<const float4*>(vvec);
#pragma unroll
        for (int e4 = 0; e4 < 8; ++e4) {
            float4 t = qg[e4];
            float q0 = ex2f(t.x * TWO_LOG2E), q1 = ex2f(t.y * TWO_LOG2E);
            float q2 = ex2f(t.z * TWO_LOG2E), q3 = ex2f(t.w * TWO_LOG2E);
            qp01[e4] = pk(q0, q1);
            qp23[e4] = pk(q2, q3);
            float4 u = vg[e4];
            vsumtot += (u.x + u.y) + (u.z + u.w);
            if (e4 < 6) {
                v0c[e4] = u.x; v1c[e4] = u.y; v2c[e4] = u.z; v3c[e4] = u.w;
                v01s[e4] = u.x + u.y; v23s[e4] = u.z + u.w;
            } else {
                vp01s[e4 - 6] = pk(u.x, u.y);
                vp23s[e4 - 6] = pk(u.z, u.w);
            }
        }
    }
    __syncthreads();

    const u64 ONES2 = pk(1.f, 1.f);

    // ---- phase 1: p = exp(score) fused; per-thread row partial sum ----
    {
        const float* maskrow = mask + (size_t)(l0 + l) * S;
        const float* klrow   = klen + (size_t)b * S;
        const float baseL = vsumtot * LOG2E;
        float psum = 0.f;
        for (int j = 0; j < S / 8; ++j) {
            int s = 8 * j + sof;
            const ulonglong2* kr = reinterpret_cast<const ulonglong2*>(ks + s * KS_STRIDE);
            float accP = 0.f;
            u64 accV = pk(0.f, 0.f);
#pragma unroll
            for (int g = 0; g < 6; ++g) {      // quad groups: 1 rcp / 4 elems
                ulonglong2 kk2 = kr[g];
                u64 uw01 = mul2(qp01[g], kk2.x);
                u64 uw23 = mul2(qp23[g], kk2.y);
                u64 A2 = add2(uw01, ONES2);    // (1+u0, 1+u1)
                u64 B2 = add2(uw23, ONES2);    // (1+u2, 1+u3)
                float u0, u1, u2, u3; upk(uw01, u0, u1); upk(uw23, u2, u3);
                float A0, A1, B0, B1; upk(A2, A0, A1); upk(B2, B0, B1);
                float denA = A0 * A1;
                float denB = B0 * B1;
                float numA = fmaf(v0c[g], u1, fmaf(v1c[g], u0, v01s[g]));
                float numB = fmaf(v2c[g], u3, fmaf(v3c[g], u2, v23s[g]));
                float num = fmaf(numA, denB, numB * denA);
                float den = denA * denB;
                accP = fmaf(num, rcpf(den), accP);
            }
#pragma unroll
            for (int g = 6; g < 8; ++g) {      // packed-simple groups
                ulonglong2 kk2 = kr[g];
                u64 d01 = fma2(qp01[g], kk2.x, ONES2);
                u64 d23 = fma2(qp23[g], kk2.y, ONES2);
                float a0, a1, a2, a3; upk(d01, a0, a1); upk(d23, a2, a3);
                u64 r01 = pk(rcpf(a0), rcpf(a1));
                u64 r23 = pk(rcpf(a2), rcpf(a3));
                accV = fma2(vp01s[g - 6], r01, accV);
                accV = fma2(vp23s[g - 6], r23, accV);
            }
            float vlo, vhi; upk(accV, vlo, vhi);
            float a = accP + (vlo + vhi);
            float mk = maskrow[s] + klrow[s];
            float p = ex2f(fmaf(-2.f * LOG2E, a, fmaf(LOG2E, mk, baseL)));
            psum += p;
            sc[l * SC_STRIDE + s] = p;
        }
        psum += __shfl_xor_sync(0xffffffffu, psum, 1);
        psum += __shfl_xor_sync(0xffffffffu, psum, 2);
        psum += __shfl_xor_sync(0xffffffffu, psum, 4);
        if (sof == 0) rsum[l] = rcpf(psum);
    }
    __syncthreads();

    // ---- phase 3: 4x8 register tile per thread, 4 s-subgroups, packed FMA ----
    {
        const int sgrp = tid >> 7;
        const int tt   = tid & 127;
        const int rg   = tt >> 3;
        const int cg   = tt & 7;

        u64 acc2[4][4];
#pragma unroll
        for (int i = 0; i < 4; ++i)
#pragma unroll
            for (int m = 0; m < 4; ++m) acc2[i][m] = pk(0.f, 0.f);

        for (int c = 0; c < 8; ++c) {
            for (int i = tid; i < 64 * (D / 4); i += THREADS) {
                int ss = i >> 4, d4 = i & 15;
                float4 t = reinterpret_cast<const float4*>(
                    vals + ((size_t)((b * S + c * 64 + ss) * H + h)) * D)[d4];
                *reinterpret_cast<float4*>(vs + ss * VS_STRIDE + d4 * 4) = t;
            }
            __syncthreads();

            const float* Pb = sc + (4 * rg) * SC_STRIDE + c * 64 + 16 * sgrp;
            const float* Vb = vs + (16 * sgrp) * VS_STRIDE + 8 * cg;
#pragma unroll
            for (int jb = 0; jb < 16; jb += 4) {
                float p4[4][4];
#pragma unroll
                for (int i = 0; i < 4; ++i) {
                    float4 p = *reinterpret_cast<const float4*>(Pb + i * SC_STRIDE + jb);
                    p4[i][0] = p.x; p4[i][1] = p.y; p4[i][2] = p.z; p4[i][3] = p.w;
                }
#pragma unroll
                for (int u = 0; u < 4; ++u) {
                    const ulonglong2* vrow =
                        reinterpret_cast<const ulonglong2*>(Vb + (jb + u) * VS_STRIDE);
                    ulonglong2 va = vrow[0];
                    ulonglong2 vb2 = vrow[1];
#pragma unroll
                    for (int i = 0; i < 4; ++i) {
                        u64 pp = pk(p4[i][u], p4[i][u]);
                        acc2[i][0] = fma2(va.x,  pp, acc2[i][0]);
                        acc2[i][1] = fma2(va.y,  pp, acc2[i][1]);
                        acc2[i][2] = fma2(vb2.x, pp, acc2[i][2]);
                        acc2[i][3] = fma2(vb2.y, pp, acc2[i][3]);
                    }
                }
            }
            __syncthreads();
        }

        float* pbuf = ks;  // [4][64][PB_STRIDE]
#pragma unroll
        for (int i = 0; i < 4; ++i) {
            int row = 4 * rg + i;
            u64* dst = reinterpret_cast<u64*>(
                pbuf + (sgrp * 64 + row) * PB_STRIDE + 8 * cg);
            reinterpret_cast<ulonglong2*>(dst)[0] = make_ulonglong2(acc2[i][0], acc2[i][1]);
            reinterpret_cast<ulonglong2*>(dst)[1] = make_ulonglong2(acc2[i][2], acc2[i][3]);
        }
        __syncthreads();

        {
            int row = tid >> 3;
            int c8  = (tid & 7) * 8;
            const float* p0 = pbuf + (0 * 64 + row) * PB_STRIDE + c8;
            const float* p1 = pbuf + (1 * 64 + row) * PB_STRIDE + c8;
            const float* p2 = pbuf + (2 * 64 + row) * PB_STRIDE + c8;
            const float* p3 = pbuf + (3 * 64 + row) * PB_STRIDE + c8;
            float r = rsum[row];
            float* og = out + ((size_t)((b * L + l0 + row) * H + h)) * D + c8;
#pragma unroll
            for (int half = 0; half < 2; ++half) {
                float4 a0 = *reinterpret_cast<const float4*>(p0 + 4 * half);
                float4 a1 = *reinterpret_cast<const float4*>(p1 + 4 * half);
                float4 a2 = *reinterpret_cast<const float4*>(p2 + 4 * half);
                float4 a3 = *reinterpret_cast<const float4*>(p3 + 4 * half);
                float4 o;
                o.x = ((a0.x + a1.x) + (a2.x + a3.x)) * r;
                o.y = ((a0.y + a1.y) + (a2.y + a3.y)) * r;
                o.z = ((a0.z + a1.z) + (a2.z + a3.z)) * r;
                o.w = ((a0.w + a1.w) + (a2.w + a3.w)) * r;
                *reinterpret_cast<float4*>(og + 4 * half) = o;
            }
        }
    }
}

extern "C" void kernel_launch(void* const* d_in, const int* in_sizes, int n_in,
                              void* d_out, int out_size)
{
    (void)in_sizes; (void)n_in; (void)out_size;
    cudaFuncSetAttribute(addattn_kernel,
                         cudaFuncAttributeMaxDynamicSharedMemorySize, SMEM_BYTES);
    const float* q    = (const float*)d_in[0];
    const float* k    = (const float*)d_in[1];
    const float* vals = (const float*)d_in[2];
    const float* vvec = (const float*)d_in[3];
    const float* mask = (const float*)d_in[4];
    const float* klen = (const float*)d_in[5];
    addattn_kernel<<<B * H * (L / TL), THREADS, SMEM_BYTES>>>(
        q, k, vals, vvec, mask, klen, (float*)d_out);
}